// round 7
// baseline (speedup 1.0000x reference)
#include <cuda_runtime.h>

#define BB 32
#define SS 2048
#define DD 1024
#define EE 16
#define KK 4
#define OO 1024
#define KD 4096
#define BS (BB*SS)

// ---------------- scratch ----------------
__device__ float g_logits[BB*EE*SS];            // [b][e][s]   4 MB
__device__ int   g_tidx[BB*EE*KK];
__device__ float g_tval[BB*EE*KK];
__device__ float g_inpT[(size_t)EE*KD*BB];      // [e][kk][m=b] 8 MB
__device__ float g_h1 [BB*EE*OO];               // [m][e][o]   2 MB
__device__ float g_h1T[EE*OO*BB];               // [e][o][m]   2 MB
__device__ float g_h2 [BB*EE*OO];
__device__ float g_h2T[EE*OO*BB];

// ---------------- helpers ----------------
union F2 { unsigned long long u; float2 f; };

__device__ __forceinline__ void ffma2(F2& acc, const F2& a, const F2& b) {
    asm("fma.rn.f32x2 %0, %1, %2, %0;" : "+l"(acc.u) : "l"(a.u), "l"(b.u));
}
__device__ __forceinline__ F2 fsplat(float v) {
    F2 r;
    asm("mov.b64 %0, {%1, %1};" : "=l"(r.u) : "r"(__float_as_uint(v)));
    return r;
}
__device__ __forceinline__ unsigned smem_u32(const void* p) {
    return (unsigned)__cvta_generic_to_shared(p);
}
__device__ __forceinline__ void cp_async16(unsigned dst, const void* src) {
    asm volatile("cp.async.cg.shared.global [%0], [%1], 16;" :: "r"(dst), "l"(src) : "memory");
}
__device__ __forceinline__ void cp_commit() {
    asm volatile("cp.async.commit_group;" ::: "memory");
}
__device__ __forceinline__ void cp_wait1() {
    asm volatile("cp.async.wait_group 1;" ::: "memory");
}

// ---------------- K1: gate logits -----------------------------------------
// logits[b][e][s] = x[b,s,:] . Wg[:,e]; 256 thr, 2 tokens/thread, grid 128.
// x streams through depth-3 cp.async ring (1 barrier/chunk); WgT preloaded
// once (pitch 1034, conflict-free). 2 tokens amortize the wt broadcast LDS
// (256 FFMA2 vs 144 LDS per chunk -> fma-bound).
#define K1_XS_PITCH 20
#define K1_XS_BUF   (512 * K1_XS_PITCH)
#define K1_WT_PITCH 1034
#define K1_SMEM_BYTES ((3 * K1_XS_BUF + EE * K1_WT_PITCH) * 4)   // 189,056

__global__ __launch_bounds__(256) void k1_logits(const float* __restrict__ x,
                                                 const float* __restrict__ Wg) {
    extern __shared__ __align__(16) float sm[];
    float* xs = sm;                        // [3][512][20]
    float* wt = sm + 3 * K1_XS_BUF;        // [16][1034]
    const int tid  = threadIdx.x;
    const int tok0 = blockIdx.x * 512;

#pragma unroll
    for (int i = 0; i < 64; i++) {
        const int g = tid + 256 * i;       // g = d*16 + e
        wt[(g & 15) * K1_WT_PITCH + (g >> 4)] = Wg[g];
    }

    auto issueChunk = [&](int c) {
        const unsigned base = smem_u32(xs + (c % 3) * K1_XS_BUF);
#pragma unroll
        for (int i = 0; i < 8; i++) {
            const int idx = tid + 256 * i;           // 0..2047
            const int tok = idx >> 2;
            const int c4  = (idx & 3) * 4;
            cp_async16(base + (tok * K1_XS_PITCH + c4) * 4,
                       x + (size_t)(tok0 + tok) * DD + c * 16 + c4);
        }
        cp_commit();
    };

    issueChunk(0);
    issueChunk(1);

    F2 acc[32];
#pragma unroll
    for (int i = 0; i < 32; i++) acc[i].u = 0ull;

    for (int dc = 0; dc < 64; dc++) {
        cp_wait1();
        __syncthreads();
        if (dc + 2 < 64) issueChunk(dc + 2); else cp_commit();

        const float* a0p = xs + (dc % 3) * K1_XS_BUF + tid * K1_XS_PITCH;
        const float* a1p = a0p + 256 * K1_XS_PITCH;
        const float* wb  = wt + dc * 16;
#pragma unroll
        for (int q = 0; q < 4; q++) {
            const F2 a00 = *(const F2*)(a0p + q * 4);
            const F2 a01 = *(const F2*)(a0p + q * 4 + 2);
            const F2 a10 = *(const F2*)(a1p + q * 4);
            const F2 a11 = *(const F2*)(a1p + q * 4 + 2);
#pragma unroll
            for (int e = 0; e < 16; e++) {
                const F2 b0 = *(const F2*)(wb + e * K1_WT_PITCH + q * 4);
                const F2 b1 = *(const F2*)(wb + e * K1_WT_PITCH + q * 4 + 2);
                ffma2(acc[e * 2 + 0], a00, b0);
                ffma2(acc[e * 2 + 0], a01, b1);
                ffma2(acc[e * 2 + 1], a10, b0);
                ffma2(acc[e * 2 + 1], a11, b1);
            }
        }
    }

    const int t0 = tok0 + tid;
    const int t1 = t0 + 256;
    const int b  = t0 >> 11;               // 512 | 2048 -> same b for both
    const int s0 = t0 & (SS - 1);
    const int s1 = t1 & (SS - 1);
#pragma unroll
    for (int e = 0; e < 16; e++) {
        g_logits[((size_t)(b * EE + e)) * SS + s0] = acc[e * 2 + 0].f.x + acc[e * 2 + 0].f.y;
        g_logits[((size_t)(b * EE + e)) * SS + s1] = acc[e * 2 + 1].f.x + acc[e * 2 + 1].f.y;
    }
}

// ---------------- K2: softmax stats + top-4 ------------------------------
__global__ void k2_topk() {
    const int pair = blockIdx.x * 8 + (threadIdx.x >> 5);   // b*16+e
    const int lane = threadIdx.x & 31;
    const float* __restrict__ L = g_logits + (size_t)pair * SS;

    float t0 = -3.402823466e38f, t1 = t0, t2 = t0, t3 = t0;
    int i0 = SS, i1 = SS, i2 = SS, i3 = SS;

#pragma unroll 8
    for (int s = lane; s < SS; s += 32) {
        const float v = L[s];
        if (v > t3) {
            if (v > t1) {
                if (v > t0) { t3=t2;i3=i2; t2=t1;i2=i1; t1=t0;i1=i0; t0=v;i0=s; }
                else        { t3=t2;i3=i2; t2=t1;i2=i1; t1=v;i1=s; }
            } else {
                if (v > t2) { t3=t2;i3=i2; t2=v;i2=s; }
                else        { t3=v;i3=s; }
            }
        }
    }

#pragma unroll
    for (int off = 16; off; off >>= 1) {
        float ov[4]; int oi[4];
        ov[0] = __shfl_xor_sync(0xffffffffu, t0, off); oi[0] = __shfl_xor_sync(0xffffffffu, i0, off);
        ov[1] = __shfl_xor_sync(0xffffffffu, t1, off); oi[1] = __shfl_xor_sync(0xffffffffu, i1, off);
        ov[2] = __shfl_xor_sync(0xffffffffu, t2, off); oi[2] = __shfl_xor_sync(0xffffffffu, i2, off);
        ov[3] = __shfl_xor_sync(0xffffffffu, t3, off); oi[3] = __shfl_xor_sync(0xffffffffu, i3, off);
#pragma unroll
        for (int c = 0; c < 4; c++) {
            const float v = ov[c]; const int ix = oi[c];
            const bool w3 = (v > t3) || (v == t3 && ix < i3);
            if (w3) {
                const bool w1 = (v > t1) || (v == t1 && ix < i1);
                if (w1) {
                    const bool w0 = (v > t0) || (v == t0 && ix < i0);
                    if (w0) { t3=t2;i3=i2; t2=t1;i2=i1; t1=t0;i1=i0; t0=v;i0=ix; }
                    else    { t3=t2;i3=i2; t2=t1;i2=i1; t1=v;i1=ix; }
                } else {
                    const bool w2 = (v > t2) || (v == t2 && ix < i2);
                    if (w2) { t3=t2;i3=i2; t2=v;i2=ix; }
                    else    { t3=v;i3=ix; }
                }
            }
        }
    }

    const float m = t0;
    float sum = 0.f;
#pragma unroll 8
    for (int s = lane; s < SS; s += 32) sum += expf(L[s] - m);
#pragma unroll
    for (int off = 16; off; off >>= 1) sum += __shfl_xor_sync(0xffffffffu, sum, off);

    if (lane == 0) {
        const float inv = 1.0f / sum;
        g_tidx[pair * 4 + 0] = i0; g_tval[pair * 4 + 0] = expf(t0 - m) * inv;
        g_tidx[pair * 4 + 1] = i1; g_tval[pair * 4 + 1] = expf(t1 - m) * inv;
        g_tidx[pair * 4 + 2] = i2; g_tval[pair * 4 + 2] = expf(t2 - m) * inv;
        g_tidx[pair * 4 + 3] = i3; g_tval[pair * 4 + 3] = expf(t3 - m) * inv;
    }
}

// ---------------- K4: gather+scale+TRANSPOSE into g_inpT ------------------
__global__ __launch_bounds__(256) void k4_gatherT(const float* __restrict__ x) {
    __shared__ float ts[32 * 257];
    const int t  = threadIdx.x;
    const int dc = blockIdx.x;
    const int kslot = blockIdx.y;
    const int e  = blockIdx.z;

    const int brow = t >> 3;
    const int d4   = (t & 7) * 4;
    const int idx  = g_tidx[((brow * EE + e)) * KK + kslot];
    const float val = g_tval[((brow * EE + e)) * KK + kslot];
    const float* src = x + ((size_t)brow * SS + idx) * DD + dc * 256;
#pragma unroll
    for (int i = 0; i < 8; i++) {
        const int d = d4 + 32 * i;
        const float4 v = *(const float4*)(src + d);
        float* dst = ts + brow * 257 + d;
        dst[0] = v.x * val; dst[1] = v.y * val; dst[2] = v.z * val; dst[3] = v.w * val;
    }
    __syncthreads();

    float* outb = g_inpT + (size_t)e * (KD * BB)
                + ((size_t)kslot * 1024 + dc * 256) * BB;
    const int bq = t & 7;
#pragma unroll
    for (int j = 0; j < 8; j++) {
        const int d = (t >> 3) + 32 * j;
        float4 v;
        v.x = ts[(bq * 4 + 0) * 257 + d];
        v.y = ts[(bq * 4 + 1) * 257 + d];
        v.z = ts[(bq * 4 + 2) * 257 + d];
        v.w = ts[(bq * 4 + 3) * 257 + d];
        *(float4*)(outb + (size_t)d * BB + bq * 4) = v;
    }
}

// ---------------- T: transpose h [m][e][o] -> hT [e][o][m] ----------------
__global__ __launch_bounds__(256) void t_transpose(const float* __restrict__ h,
                                                   float* __restrict__ hT) {
    __shared__ float ts[32 * 257];
    const int t  = threadIdx.x;
    const int oc = blockIdx.x;
    const int e  = blockIdx.y;

    const int mrow = t >> 3;
    const int o4   = (t & 7) * 4;
    const float* src = h + ((size_t)mrow * EE + e) * OO + oc * 256;
#pragma unroll
    for (int i = 0; i < 8; i++) {
        const int o = o4 + 32 * i;
        const float4 v = *(const float4*)(src + o);
        float* dst = ts + mrow * 257 + o;
        dst[0] = v.x; dst[1] = v.y; dst[2] = v.z; dst[3] = v.w;
    }
    __syncthreads();

    float* outb = hT + (size_t)e * (OO * BB) + (size_t)(oc * 256) * BB;
    const int mq = t & 7;
#pragma unroll
    for (int j = 0; j < 8; j++) {
        const int o = (t >> 3) + 32 * j;
        float4 v;
        v.x = ts[(mq * 4 + 0) * 257 + o];
        v.y = ts[(mq * 4 + 1) * 257 + o];
        v.z = ts[(mq * 4 + 2) * 257 + o];
        v.w = ts[(mq * 4 + 3) * 257 + o];
        *(float4*)(outb + (size_t)o * BB + mq * 4) = v;
    }
}

// ---------------- grouped GEMM -------------------------------------------
// Out[m=32,1024] = AT[e][KDIM][32] x W[e][KDIM,1024]  (+bias, relu?)
// grid (8 otiles, 16 experts), 512 thr = 16 warps: warp = (rg, ks).
// BOTH A and W stream through one cp.async depth-3 smem ring, chunk = 8 j
// per K-slice (A slot 8KB + W slot 32KB). One commit/wait/barrier per chunk
// -> lookahead 2 chunks (~4000 cyc) hides DRAM; no per-j cp ops.
// Inner j: 8 broadcast LDS.64 (A) + 1 LDS.128 (W) + 4 splats + 32 FFMA2.
#define CJ 8
#define A_SLOT (8 * CJ * 32)                       // 2048 floats
#define W_SLOT (8 * CJ * 128)                      // 8192 floats
#define RING_SLOT (A_SLOT + W_SLOT)                // 10240 floats
#define GEMM_SMEM_BYTES (3 * RING_SLOT * 4)        // 122,880

template <int KDIM>
__global__ __launch_bounds__(512) void gemm_kernel(const float* __restrict__ AT,
                                                   const float* __restrict__ W,
                                                   const float* __restrict__ bias,
                                                   float* __restrict__ Out,
                                                   int doRelu) {
    constexpr int KPS    = KDIM / 8;
    constexpr int CHUNKS = KPS / CJ;
    extern __shared__ __align__(16) float sm[];

    const int tid  = threadIdx.x;
    const int lane = tid & 31;
    const int w    = tid >> 5;
    const int rg   = w & 1;
    const int ks   = w >> 1;
    const int e    = blockIdx.y;
    const float* Ab = AT + (size_t)e * KDIM * BB;
    const float* Wb = W + (size_t)e * KDIM * OO + blockIdx.x * 128;

    // slot layout: A [slice*CJ+j][m 0..31] then W [slice*CJ+j][col 0..127]
    auto issueChunk = [&](int c) {
        const unsigned base = smem_u32(sm + (c % 3) * RING_SLOT);
        // A: 512 float4, 1 per thread
        {
            const int kk = tid >> 3;               // 0..63 = slice*CJ + j
            const int m4 = (tid & 7) * 4;
            cp_async16(base + (kk * 32 + m4) * 4,
                       Ab + ((size_t)(kk >> 3) * KPS + c * CJ + (kk & 7)) * BB + m4);
        }
        // W: 2048 float4, 4 per thread
#pragma unroll
        for (int i = 0; i < 4; i++) {
            const int f    = tid + 512 * i;        // 0..2047
            const int kk   = f >> 5;               // 0..63
            const int col4 = (f & 31) * 4;
            cp_async16(base + (A_SLOT + kk * 128 + col4) * 4,
                       Wb + ((size_t)(kk >> 3) * KPS + c * CJ + (kk & 7)) * OO + col4);
        }
        cp_commit();
    };

    issueChunk(0);
    issueChunk(1);

    F2 acc[32];
#pragma unroll
    for (int i = 0; i < 32; i++) acc[i].u = 0ull;

    for (int c = 0; c < CHUNKS; c++) {
        cp_wait1();
        __syncthreads();
        if (c + 2 < CHUNKS) issueChunk(c + 2); else cp_commit();

        const float* slot = sm + (c % 3) * RING_SLOT;
        const float* As = slot + (ks * CJ) * 32 + rg * 16;
        const float* Ws = slot + A_SLOT + (ks * CJ) * 128 + lane * 4;
#pragma unroll
        for (int j = 0; j < CJ; j++) {
            const float4 q = *(const float4*)(Ws + j * 128);      // LDS.128
            const F2* ar = (const F2*)(As + j * 32);
            const F2 b0 = fsplat(q.x), b1 = fsplat(q.y),
                     b2 = fsplat(q.z), b3 = fsplat(q.w);
#pragma unroll
            for (int rp = 0; rp < 8; rp++) {
                const F2 a = ar[rp];               // broadcast LDS.64
                ffma2(acc[rp * 4 + 0], a, b0);
                ffma2(acc[rp * 4 + 1], a, b1);
                ffma2(acc[rp * 4 + 2], a, b2);
                ffma2(acc[rp * 4 + 3], a, b3);
            }
        }
    }

    // epilogue: reduce 8 K-slices via smem, bias (+relu), store [m][e][o]
    F2* buf = (F2*)sm;
#pragma unroll
    for (int rp = 0; rp < 8; rp++) {
        __syncthreads();
#pragma unroll
        for (int c = 0; c < 4; c++)
            buf[((ks * 2 + rg) * 32 + lane) * 4 + c] = acc[rp * 4 + c];
        __syncthreads();
        if (tid < 256) {
            const int rrg = tid >> 7;
            const int col = tid & 127;
            const int li  = col >> 2;
            const int ci  = col & 3;
            float sx = 0.f, sy = 0.f;
#pragma unroll
            for (int kss = 0; kss < 8; kss++) {
                const F2 v = buf[((kss * 2 + rrg) * 32 + li) * 4 + ci];
                sx += v.f.x; sy += v.f.y;
            }
            const int occol = blockIdx.x * 128 + col;
            const float bv = bias[e * OO + occol];
            sx += bv; sy += bv;
            if (doRelu) { sx = fmaxf(sx, 0.f); sy = fmaxf(sy, 0.f); }
            const int r0 = rrg * 16 + 2 * rp;
            Out[((size_t)r0 * EE + e) * OO + occol] = sx;
            Out[((size_t)(r0 + 1) * EE + e) * OO + occol] = sy;
        }
    }
}

// ---------------- launch ----------------
extern "C" void kernel_launch(void* const* d_in, const int* in_sizes, int n_in,
                              void* d_out, int out_size) {
    const float* x  = (const float*)d_in[0];
    const float* Wg = (const float*)d_in[1];
    // d_in[2] = bg: constant over the softmax (token) axis -> cancels exactly.
    const float* W1 = (const float*)d_in[3];
    const float* b1 = (const float*)d_in[4];
    const float* W2 = (const float*)d_in[5];
    const float* b2 = (const float*)d_in[6];
    const float* W3 = (const float*)d_in[7];
    const float* b3 = (const float*)d_in[8];
    float* out = (float*)d_out;

    void *pInpT=nullptr, *pH1=nullptr, *pH1T=nullptr, *pH2=nullptr, *pH2T=nullptr;
    cudaGetSymbolAddress(&pInpT, g_inpT);
    cudaGetSymbolAddress(&pH1,  g_h1);
    cudaGetSymbolAddress(&pH1T, g_h1T);
    cudaGetSymbolAddress(&pH2,  g_h2);
    cudaGetSymbolAddress(&pH2T, g_h2T);

    cudaFuncSetAttribute(k1_logits, cudaFuncAttributeMaxDynamicSharedMemorySize, K1_SMEM_BYTES);
    cudaFuncSetAttribute(gemm_kernel<KD>, cudaFuncAttributeMaxDynamicSharedMemorySize, GEMM_SMEM_BYTES);
    cudaFuncSetAttribute(gemm_kernel<OO>, cudaFuncAttributeMaxDynamicSharedMemorySize, GEMM_SMEM_BYTES);

    k1_logits<<<BS / 512, 256, K1_SMEM_BYTES>>>(x, Wg);
    k2_topk<<<(BB * EE) / 8, 256>>>();
    k4_gatherT<<<dim3(4, KK, EE), 256>>>(x);
    gemm_kernel<KD><<<dim3(8, EE), 512, GEMM_SMEM_BYTES>>>((const float*)pInpT, W1, b1, (float*)pH1, 1);
    t_transpose<<<dim3(4, EE), 256>>>((const float*)pH1, (float*)pH1T);
    gemm_kernel<OO><<<dim3(8, EE), 512, GEMM_SMEM_BYTES>>>((const float*)pH1T, W2, b2, (float*)pH2, 1);
    t_transpose<<<dim3(4, EE), 256>>>((const float*)pH2, (float*)pH2T);
    gemm_kernel<OO><<<dim3(8, EE), 512, GEMM_SMEM_BYTES>>>((const float*)pH2T, W3, b3, out, 0);
}

// round 8
// speedup vs baseline: 1.0593x; 1.0593x over previous
#include <cuda_runtime.h>

#define BB 32
#define SS 2048
#define DD 1024
#define EE 16
#define KK 4
#define OO 1024
#define KD 4096
#define BS (BB*SS)

// ---------------- scratch ----------------
__device__ float g_logits[BB*EE*SS];            // [b][e][s]   4 MB
__device__ int   g_tidx[BB*EE*KK];
__device__ float g_tval[BB*EE*KK];
__device__ float g_inpT[(size_t)EE*KD*BB];      // [e][kk][m=b] 8 MB
__device__ float g_h1 [BB*EE*OO];               // [m][e][o]   2 MB
__device__ float g_h1T[EE*OO*BB];               // [e][o][m]   2 MB
__device__ float g_h2 [BB*EE*OO];
__device__ float g_h2T[EE*OO*BB];

// ---------------- helpers ----------------
union F2 { unsigned long long u; float2 f; };

__device__ __forceinline__ void ffma2(F2& acc, const F2& a, const F2& b) {
    asm("fma.rn.f32x2 %0, %1, %2, %0;" : "+l"(acc.u) : "l"(a.u), "l"(b.u));
}
__device__ __forceinline__ F2 fsplat(float v) {
    F2 r;
    asm("mov.b64 %0, {%1, %1};" : "=l"(r.u) : "r"(__float_as_uint(v)));
    return r;
}
__device__ __forceinline__ unsigned smem_u32(const void* p) {
    return (unsigned)__cvta_generic_to_shared(p);
}
__device__ __forceinline__ void cp_async16(unsigned dst, const void* src) {
    asm volatile("cp.async.cg.shared.global [%0], [%1], 16;" :: "r"(dst), "l"(src) : "memory");
}
__device__ __forceinline__ void cp_commit() {
    asm volatile("cp.async.commit_group;" ::: "memory");
}
__device__ __forceinline__ void cp_wait1() {
    asm volatile("cp.async.wait_group 1;" ::: "memory");
}

// ---------------- K1: gate logits -----------------------------------------
// logits[b][e][s] = x[b,s,:] . Wg[:,e]; 256 thr, 2 tokens/thread, grid 128.
#define K1_XS_PITCH 20
#define K1_XS_BUF   (512 * K1_XS_PITCH)
#define K1_WT_PITCH 1034
#define K1_SMEM_BYTES ((3 * K1_XS_BUF + EE * K1_WT_PITCH) * 4)   // 189,056

__global__ __launch_bounds__(256) void k1_logits(const float* __restrict__ x,
                                                 const float* __restrict__ Wg) {
    extern __shared__ __align__(16) float sm[];
    float* xs = sm;                        // [3][512][20]
    float* wt = sm + 3 * K1_XS_BUF;        // [16][1034]
    const int tid  = threadIdx.x;
    const int tok0 = blockIdx.x * 512;

#pragma unroll
    for (int i = 0; i < 64; i++) {
        const int g = tid + 256 * i;       // g = d*16 + e
        wt[(g & 15) * K1_WT_PITCH + (g >> 4)] = Wg[g];
    }

    // running-pointer chunk issue (advance by 16 floats per chunk)
    const int xtok = tid >> 2;
    const int xc4  = (tid & 3) * 4;
    const float* xsrc[8];
    unsigned xdst[8];
#pragma unroll
    for (int i = 0; i < 8; i++) {
        const int idx = tid + 256 * i;
        const int tok = idx >> 2;
        const int c4  = (idx & 3) * 4;
        xsrc[i] = x + (size_t)(tok0 + tok) * DD + c4;
        xdst[i] = (tok * K1_XS_PITCH + c4) * 4;
    }
    const unsigned xsBase = smem_u32(xs);
    int pslot = 0;
    auto issueChunk = [&]() {
        const unsigned base = xsBase + pslot * (K1_XS_BUF * 4);
#pragma unroll
        for (int i = 0; i < 8; i++) {
            cp_async16(base + xdst[i], xsrc[i]);
            xsrc[i] += 16;
        }
        cp_commit();
        pslot = (pslot == 2) ? 0 : pslot + 1;
    };

    issueChunk();
    issueChunk();

    F2 acc[32];
#pragma unroll
    for (int i = 0; i < 32; i++) acc[i].u = 0ull;

    int cslot = 0;
    for (int dc = 0; dc < 64; dc++) {
        cp_wait1();
        __syncthreads();
        if (dc + 2 < 64) issueChunk(); else cp_commit();

        const float* a0p = xs + cslot * K1_XS_BUF + tid * K1_XS_PITCH;
        const float* a1p = a0p + 256 * K1_XS_PITCH;
        const float* wb  = wt + dc * 16;
        cslot = (cslot == 2) ? 0 : cslot + 1;
#pragma unroll
        for (int q = 0; q < 4; q++) {
            const F2 a00 = *(const F2*)(a0p + q * 4);
            const F2 a01 = *(const F2*)(a0p + q * 4 + 2);
            const F2 a10 = *(const F2*)(a1p + q * 4);
            const F2 a11 = *(const F2*)(a1p + q * 4 + 2);
#pragma unroll
            for (int e = 0; e < 16; e++) {
                const F2 b0 = *(const F2*)(wb + e * K1_WT_PITCH + q * 4);
                const F2 b1 = *(const F2*)(wb + e * K1_WT_PITCH + q * 4 + 2);
                ffma2(acc[e * 2 + 0], a00, b0);
                ffma2(acc[e * 2 + 0], a01, b1);
                ffma2(acc[e * 2 + 1], a10, b0);
                ffma2(acc[e * 2 + 1], a11, b1);
            }
        }
    }

    const int t0 = tok0 + tid;
    const int t1 = t0 + 256;
    const int b  = t0 >> 11;
    const int s0 = t0 & (SS - 1);
    const int s1 = t1 & (SS - 1);
#pragma unroll
    for (int e = 0; e < 16; e++) {
        g_logits[((size_t)(b * EE + e)) * SS + s0] = acc[e * 2 + 0].f.x + acc[e * 2 + 0].f.y;
        g_logits[((size_t)(b * EE + e)) * SS + s1] = acc[e * 2 + 1].f.x + acc[e * 2 + 1].f.y;
    }
}

// ---------------- K2: softmax stats + top-4 ------------------------------
__global__ void k2_topk() {
    const int pair = blockIdx.x * 8 + (threadIdx.x >> 5);   // b*16+e
    const int lane = threadIdx.x & 31;
    const float* __restrict__ L = g_logits + (size_t)pair * SS;

    float t0 = -3.402823466e38f, t1 = t0, t2 = t0, t3 = t0;
    int i0 = SS, i1 = SS, i2 = SS, i3 = SS;

#pragma unroll 8
    for (int s = lane; s < SS; s += 32) {
        const float v = L[s];
        if (v > t3) {
            if (v > t1) {
                if (v > t0) { t3=t2;i3=i2; t2=t1;i2=i1; t1=t0;i1=i0; t0=v;i0=s; }
                else        { t3=t2;i3=i2; t2=t1;i2=i1; t1=v;i1=s; }
            } else {
                if (v > t2) { t3=t2;i3=i2; t2=v;i2=s; }
                else        { t3=v;i3=s; }
            }
        }
    }

#pragma unroll
    for (int off = 16; off; off >>= 1) {
        float ov[4]; int oi[4];
        ov[0] = __shfl_xor_sync(0xffffffffu, t0, off); oi[0] = __shfl_xor_sync(0xffffffffu, i0, off);
        ov[1] = __shfl_xor_sync(0xffffffffu, t1, off); oi[1] = __shfl_xor_sync(0xffffffffu, i1, off);
        ov[2] = __shfl_xor_sync(0xffffffffu, t2, off); oi[2] = __shfl_xor_sync(0xffffffffu, i2, off);
        ov[3] = __shfl_xor_sync(0xffffffffu, t3, off); oi[3] = __shfl_xor_sync(0xffffffffu, i3, off);
#pragma unroll
        for (int c = 0; c < 4; c++) {
            const float v = ov[c]; const int ix = oi[c];
            const bool w3 = (v > t3) || (v == t3 && ix < i3);
            if (w3) {
                const bool w1 = (v > t1) || (v == t1 && ix < i1);
                if (w1) {
                    const bool w0 = (v > t0) || (v == t0 && ix < i0);
                    if (w0) { t3=t2;i3=i2; t2=t1;i2=i1; t1=t0;i1=i0; t0=v;i0=ix; }
                    else    { t3=t2;i3=i2; t2=t1;i2=i1; t1=v;i1=ix; }
                } else {
                    const bool w2 = (v > t2) || (v == t2 && ix < i2);
                    if (w2) { t3=t2;i3=i2; t2=v;i2=ix; }
                    else    { t3=v;i3=ix; }
                }
            }
        }
    }

    const float m = t0;
    float sum = 0.f;
#pragma unroll 8
    for (int s = lane; s < SS; s += 32) sum += expf(L[s] - m);
#pragma unroll
    for (int off = 16; off; off >>= 1) sum += __shfl_xor_sync(0xffffffffu, sum, off);

    if (lane == 0) {
        const float inv = 1.0f / sum;
        g_tidx[pair * 4 + 0] = i0; g_tval[pair * 4 + 0] = expf(t0 - m) * inv;
        g_tidx[pair * 4 + 1] = i1; g_tval[pair * 4 + 1] = expf(t1 - m) * inv;
        g_tidx[pair * 4 + 2] = i2; g_tval[pair * 4 + 2] = expf(t2 - m) * inv;
        g_tidx[pair * 4 + 3] = i3; g_tval[pair * 4 + 3] = expf(t3 - m) * inv;
    }
}

// ---------------- K4: gather+scale+TRANSPOSE into g_inpT ------------------
__global__ __launch_bounds__(256) void k4_gatherT(const float* __restrict__ x) {
    __shared__ float ts[32 * 257];
    const int t  = threadIdx.x;
    const int dc = blockIdx.x;
    const int kslot = blockIdx.y;
    const int e  = blockIdx.z;

    const int brow = t >> 3;
    const int d4   = (t & 7) * 4;
    const int idx  = g_tidx[((brow * EE + e)) * KK + kslot];
    const float val = g_tval[((brow * EE + e)) * KK + kslot];
    const float* src = x + ((size_t)brow * SS + idx) * DD + dc * 256;
#pragma unroll
    for (int i = 0; i < 8; i++) {
        const int d = d4 + 32 * i;
        const float4 v = *(const float4*)(src + d);
        float* dst = ts + brow * 257 + d;
        dst[0] = v.x * val; dst[1] = v.y * val; dst[2] = v.z * val; dst[3] = v.w * val;
    }
    __syncthreads();

    float* outb = g_inpT + (size_t)e * (KD * BB)
                + ((size_t)kslot * 1024 + dc * 256) * BB;
    const int bq = t & 7;
#pragma unroll
    for (int j = 0; j < 8; j++) {
        const int d = (t >> 3) + 32 * j;
        float4 v;
        v.x = ts[(bq * 4 + 0) * 257 + d];
        v.y = ts[(bq * 4 + 1) * 257 + d];
        v.z = ts[(bq * 4 + 2) * 257 + d];
        v.w = ts[(bq * 4 + 3) * 257 + d];
        *(float4*)(outb + (size_t)d * BB + bq * 4) = v;
    }
}

// ---------------- T: transpose h [m][e][o] -> hT [e][o][m] ----------------
__global__ __launch_bounds__(256) void t_transpose(const float* __restrict__ h,
                                                   float* __restrict__ hT) {
    __shared__ float ts[32 * 257];
    const int t  = threadIdx.x;
    const int oc = blockIdx.x;
    const int e  = blockIdx.y;

    const int mrow = t >> 3;
    const int o4   = (t & 7) * 4;
    const float* src = h + ((size_t)mrow * EE + e) * OO + oc * 256;
#pragma unroll
    for (int i = 0; i < 8; i++) {
        const int o = o4 + 32 * i;
        const float4 v = *(const float4*)(src + o);
        float* dst = ts + mrow * 257 + o;
        dst[0] = v.x; dst[1] = v.y; dst[2] = v.z; dst[3] = v.w;
    }
    __syncthreads();

    float* outb = hT + (size_t)e * (OO * BB) + (size_t)(oc * 256) * BB;
    const int mq = t & 7;
#pragma unroll
    for (int j = 0; j < 8; j++) {
        const int o = (t >> 3) + 32 * j;
        float4 v;
        v.x = ts[(mq * 4 + 0) * 257 + o];
        v.y = ts[(mq * 4 + 1) * 257 + o];
        v.z = ts[(mq * 4 + 2) * 257 + o];
        v.w = ts[(mq * 4 + 3) * 257 + o];
        *(float4*)(outb + (size_t)o * BB + mq * 4) = v;
    }
}

// ---------------- grouped GEMM -------------------------------------------
// Out[m=32,1024] = AT[e][KDIM][32] x W[e][KDIM,1024]  (+bias, relu?)
// A and W stream through one cp.async depth-3 smem ring (chunk = 8 j per
// K-slice). All cp.async addressing via RUNNING POINTERS precomputed per
// thread (no per-chunk IMAD recompute). Inner j: 8 broadcast LDS.64 +
// 1 LDS.128 + 4 splats + 32 FFMA2.
#define CJ 8
#define A_SLOT (8 * CJ * 32)                       // 2048 floats
#define W_SLOT (8 * CJ * 128)                      // 8192 floats
#define RING_SLOT (A_SLOT + W_SLOT)                // 10240 floats
#define GEMM_SMEM_BYTES (3 * RING_SLOT * 4)        // 122,880

template <int KDIM>
__global__ __launch_bounds__(512) void gemm_kernel(const float* __restrict__ AT,
                                                   const float* __restrict__ W,
                                                   const float* __restrict__ bias,
                                                   float* __restrict__ Out,
                                                   int doRelu) {
    constexpr int KPS    = KDIM / 8;
    constexpr int CHUNKS = KPS / CJ;
    extern __shared__ __align__(16) float sm[];

    const int tid  = threadIdx.x;
    const int lane = tid & 31;
    const int w    = tid >> 5;
    const int rg   = w & 1;
    const int ks   = w >> 1;
    const int e    = blockIdx.y;
    const float* Ab = AT + (size_t)e * KDIM * BB;
    const float* Wb = W + (size_t)e * KDIM * OO + blockIdx.x * 128;

    // per-thread cp.async plumbing (precomputed once)
    const int kkA = tid >> 3;                      // 0..63 = slice*CJ + j
    const int m4A = (tid & 7) * 4;
    const float* srcA = Ab + ((size_t)(kkA >> 3) * KPS + (kkA & 7)) * BB + m4A;
    const unsigned dstA = (unsigned)(kkA * 32 + m4A) * 4;
    const float* srcW[4];
    unsigned dstW[4];
#pragma unroll
    for (int i = 0; i < 4; i++) {
        const int f    = tid + 512 * i;            // 0..2047
        const int kk   = f >> 5;                   // 0..63
        const int col4 = (f & 31) * 4;
        srcW[i] = Wb + ((size_t)(kk >> 3) * KPS + (kk & 7)) * OO + col4;
        dstW[i] = (unsigned)(A_SLOT + kk * 128 + col4) * 4;
    }
    const unsigned smBase = smem_u32(sm);

    int pslot = 0;
    auto issueChunk = [&]() {
        const unsigned base = smBase + pslot * (RING_SLOT * 4);
        cp_async16(base + dstA, srcA);
        srcA += CJ * BB;
#pragma unroll
        for (int i = 0; i < 4; i++) {
            cp_async16(base + dstW[i], srcW[i]);
            srcW[i] += CJ * OO;
        }
        cp_commit();
        pslot = (pslot == 2) ? 0 : pslot + 1;
    };

    issueChunk();
    issueChunk();

    F2 acc[32];
#pragma unroll
    for (int i = 0; i < 32; i++) acc[i].u = 0ull;

    int cslot = 0;
    for (int c = 0; c < CHUNKS; c++) {
        cp_wait1();
        __syncthreads();
        if (c + 2 < CHUNKS) issueChunk(); else cp_commit();

        const float* slot = sm + cslot * RING_SLOT;
        cslot = (cslot == 2) ? 0 : cslot + 1;
        const float* As = slot + (ks * CJ) * 32 + rg * 16;
        const float* Ws = slot + A_SLOT + (ks * CJ) * 128 + lane * 4;
#pragma unroll
        for (int j = 0; j < CJ; j++) {
            const float4 q = *(const float4*)(Ws + j * 128);      // LDS.128
            const F2* ar = (const F2*)(As + j * 32);
            const F2 b0 = fsplat(q.x), b1 = fsplat(q.y),
                     b2 = fsplat(q.z), b3 = fsplat(q.w);
#pragma unroll
            for (int rp = 0; rp < 8; rp++) {
                const F2 a = ar[rp];               // broadcast LDS.64
                ffma2(acc[rp * 4 + 0], a, b0);
                ffma2(acc[rp * 4 + 1], a, b1);
                ffma2(acc[rp * 4 + 2], a, b2);
                ffma2(acc[rp * 4 + 3], a, b3);
            }
        }
    }

    // epilogue: reduce 8 K-slices via smem, bias (+relu), store [m][e][o]
    F2* buf = (F2*)sm;
#pragma unroll
    for (int rp = 0; rp < 8; rp++) {
        __syncthreads();
#pragma unroll
        for (int c = 0; c < 4; c++)
            buf[((ks * 2 + rg) * 32 + lane) * 4 + c] = acc[rp * 4 + c];
        __syncthreads();
        if (tid < 256) {
            const int rrg = tid >> 7;
            const int col = tid & 127;
            const int li  = col >> 2;
            const int ci  = col & 3;
            float sx = 0.f, sy = 0.f;
#pragma unroll
            for (int kss = 0; kss < 8; kss++) {
                const F2 v = buf[((kss * 2 + rrg) * 32 + li) * 4 + ci];
                sx += v.f.x; sy += v.f.y;
            }
            const int occol = blockIdx.x * 128 + col;
            const float bv = bias[e * OO + occol];
            sx += bv; sy += bv;
            if (doRelu) { sx = fmaxf(sx, 0.f); sy = fmaxf(sy, 0.f); }
            const int r0 = rrg * 16 + 2 * rp;
            Out[((size_t)r0 * EE + e) * OO + occol] = sx;
            Out[((size_t)(r0 + 1) * EE + e) * OO + occol] = sy;
        }
    }
}

// ---------------- launch ----------------
extern "C" void kernel_launch(void* const* d_in, const int* in_sizes, int n_in,
                              void* d_out, int out_size) {
    const float* x  = (const float*)d_in[0];
    const float* Wg = (const float*)d_in[1];
    // d_in[2] = bg: constant over the softmax (token) axis -> cancels exactly.
    const float* W1 = (const float*)d_in[3];
    const float* b1 = (const float*)d_in[4];
    const float* W2 = (const float*)d_in[5];
    const float* b2 = (const float*)d_in[6];
    const float* W3 = (const float*)d_in[7];
    const float* b3 = (const float*)d_in[8];
    float* out = (float*)d_out;

    void *pInpT=nullptr, *pH1=nullptr, *pH1T=nullptr, *pH2=nullptr, *pH2T=nullptr;
    cudaGetSymbolAddress(&pInpT, g_inpT);
    cudaGetSymbolAddress(&pH1,  g_h1);
    cudaGetSymbolAddress(&pH1T, g_h1T);
    cudaGetSymbolAddress(&pH2,  g_h2);
    cudaGetSymbolAddress(&pH2T, g_h2T);

    cudaFuncSetAttribute(k1_logits, cudaFuncAttributeMaxDynamicSharedMemorySize, K1_SMEM_BYTES);
    cudaFuncSetAttribute(gemm_kernel<KD>, cudaFuncAttributeMaxDynamicSharedMemorySize, GEMM_SMEM_BYTES);
    cudaFuncSetAttribute(gemm_kernel<OO>, cudaFuncAttributeMaxDynamicSharedMemorySize, GEMM_SMEM_BYTES);

    k1_logits<<<BS / 512, 256, K1_SMEM_BYTES>>>(x, Wg);
    k2_topk<<<(BB * EE) / 8, 256>>>();
    k4_gatherT<<<dim3(4, KK, EE), 256>>>(x);
    gemm_kernel<KD><<<dim3(8, EE), 512, GEMM_SMEM_BYTES>>>((const float*)pInpT, W1, b1, (float*)pH1, 1);
    t_transpose<<<dim3(4, EE), 256>>>((const float*)pH1, (float*)pH1T);
    gemm_kernel<OO><<<dim3(8, EE), 512, GEMM_SMEM_BYTES>>>((const float*)pH1T, W2, b2, (float*)pH2, 1);
    t_transpose<<<dim3(4, EE), 256>>>((const float*)pH2, (float*)pH2T);
    gemm_kernel<OO><<<dim3(8, EE), 512, GEMM_SMEM_BYTES>>>((const float*)pH2T, W3, b3, out, 0);
}

// round 9
// speedup vs baseline: 1.1269x; 1.0638x over previous
#include <cuda_runtime.h>

#define BB 32
#define SS 2048
#define DD 1024
#define EE 16
#define KK 4
#define OO 1024
#define KD 4096
#define BS (BB*SS)

// ---------------- scratch ----------------
__device__ float g_logits[BB*EE*SS];            // [b][e][s]   4 MB
__device__ int   g_tidx[BB*EE*KK];
__device__ float g_tval[BB*EE*KK];
__device__ float g_inpT[(size_t)EE*KD*BB];      // [e][kk][m=b] 8 MB
__device__ float g_h1 [BB*EE*OO];               // [m][e][o]   2 MB
__device__ float g_h1T[EE*OO*BB];               // [e][o][m]   2 MB
__device__ float g_h2 [BB*EE*OO];
__device__ float g_h2T[EE*OO*BB];

// ---------------- helpers ----------------
union F2 { unsigned long long u; float2 f; };

__device__ __forceinline__ void ffma2(F2& acc, const F2& a, const F2& b) {
    asm("fma.rn.f32x2 %0, %1, %2, %0;" : "+l"(acc.u) : "l"(a.u), "l"(b.u));
}
__device__ __forceinline__ F2 fsplat(float v) {
    F2 r;
    asm("mov.b64 %0, {%1, %1};" : "=l"(r.u) : "r"(__float_as_uint(v)));
    return r;
}
__device__ __forceinline__ unsigned smem_u32(const void* p) {
    return (unsigned)__cvta_generic_to_shared(p);
}
__device__ __forceinline__ void cp_async16(unsigned dst, const void* src) {
    asm volatile("cp.async.cg.shared.global [%0], [%1], 16;" :: "r"(dst), "l"(src) : "memory");
}
__device__ __forceinline__ void cp_commit() {
    asm volatile("cp.async.commit_group;" ::: "memory");
}
__device__ __forceinline__ void cp_wait1() {
    asm volatile("cp.async.wait_group 1;" ::: "memory");
}
__device__ __forceinline__ void cp_wait0() {
    asm volatile("cp.async.wait_group 0;" ::: "memory");
}

// ---------------- K1: gate logits -----------------------------------------
// logits[b][e][s] = x[b,s,:] . Wg[:,e]; 256 thr, 2 tokens/thread, grid 128.
#define K1_XS_PITCH 20
#define K1_XS_BUF   (512 * K1_XS_PITCH)
#define K1_WT_PITCH 1034
#define K1_SMEM_BYTES ((3 * K1_XS_BUF + EE * K1_WT_PITCH) * 4)   // 189,056

__global__ __launch_bounds__(256) void k1_logits(const float* __restrict__ x,
                                                 const float* __restrict__ Wg) {
    extern __shared__ __align__(16) float sm[];
    float* xs = sm;                        // [3][512][20]
    float* wt = sm + 3 * K1_XS_BUF;        // [16][1034]
    const int tid  = threadIdx.x;
    const int tok0 = blockIdx.x * 512;

#pragma unroll
    for (int i = 0; i < 64; i++) {
        const int g = tid + 256 * i;       // g = d*16 + e
        wt[(g & 15) * K1_WT_PITCH + (g >> 4)] = Wg[g];
    }

    const float* xsrc[8];
    unsigned xdst[8];
#pragma unroll
    for (int i = 0; i < 8; i++) {
        const int idx = tid + 256 * i;
        const int tok = idx >> 2;
        const int c4  = (idx & 3) * 4;
        xsrc[i] = x + (size_t)(tok0 + tok) * DD + c4;
        xdst[i] = (tok * K1_XS_PITCH + c4) * 4;
    }
    const unsigned xsBase = smem_u32(xs);
    int pslot = 0;
    auto issueChunk = [&]() {
        const unsigned base = xsBase + pslot * (K1_XS_BUF * 4);
#pragma unroll
        for (int i = 0; i < 8; i++) {
            cp_async16(base + xdst[i], xsrc[i]);
            xsrc[i] += 16;
        }
        cp_commit();
        pslot = (pslot == 2) ? 0 : pslot + 1;
    };

    issueChunk();
    issueChunk();

    F2 acc[32];
#pragma unroll
    for (int i = 0; i < 32; i++) acc[i].u = 0ull;

    int cslot = 0;
    for (int dc = 0; dc < 64; dc++) {
        cp_wait1();
        __syncthreads();
        if (dc + 2 < 64) issueChunk(); else cp_commit();

        const float* a0p = xs + cslot * K1_XS_BUF + tid * K1_XS_PITCH;
        const float* a1p = a0p + 256 * K1_XS_PITCH;
        const float* wb  = wt + dc * 16;
        cslot = (cslot == 2) ? 0 : cslot + 1;
#pragma unroll
        for (int q = 0; q < 4; q++) {
            const F2 a00 = *(const F2*)(a0p + q * 4);
            const F2 a01 = *(const F2*)(a0p + q * 4 + 2);
            const F2 a10 = *(const F2*)(a1p + q * 4);
            const F2 a11 = *(const F2*)(a1p + q * 4 + 2);
#pragma unroll
            for (int e = 0; e < 16; e++) {
                const F2 b0 = *(const F2*)(wb + e * K1_WT_PITCH + q * 4);
                const F2 b1 = *(const F2*)(wb + e * K1_WT_PITCH + q * 4 + 2);
                ffma2(acc[e * 2 + 0], a00, b0);
                ffma2(acc[e * 2 + 0], a01, b1);
                ffma2(acc[e * 2 + 1], a10, b0);
                ffma2(acc[e * 2 + 1], a11, b1);
            }
        }
    }

    const int t0 = tok0 + tid;
    const int t1 = t0 + 256;
    const int b  = t0 >> 11;
    const int s0 = t0 & (SS - 1);
    const int s1 = t1 & (SS - 1);
#pragma unroll
    for (int e = 0; e < 16; e++) {
        g_logits[((size_t)(b * EE + e)) * SS + s0] = acc[e * 2 + 0].f.x + acc[e * 2 + 0].f.y;
        g_logits[((size_t)(b * EE + e)) * SS + s1] = acc[e * 2 + 1].f.x + acc[e * 2 + 1].f.y;
    }
}

// ---------------- K2: softmax stats + top-4 ------------------------------
__global__ void k2_topk() {
    const int pair = blockIdx.x * 8 + (threadIdx.x >> 5);   // b*16+e
    const int lane = threadIdx.x & 31;
    const float* __restrict__ L = g_logits + (size_t)pair * SS;

    float t0 = -3.402823466e38f, t1 = t0, t2 = t0, t3 = t0;
    int i0 = SS, i1 = SS, i2 = SS, i3 = SS;

#pragma unroll 8
    for (int s = lane; s < SS; s += 32) {
        const float v = L[s];
        if (v > t3) {
            if (v > t1) {
                if (v > t0) { t3=t2;i3=i2; t2=t1;i2=i1; t1=t0;i1=i0; t0=v;i0=s; }
                else        { t3=t2;i3=i2; t2=t1;i2=i1; t1=v;i1=s; }
            } else {
                if (v > t2) { t3=t2;i3=i2; t2=v;i2=s; }
                else        { t3=v;i3=s; }
            }
        }
    }

#pragma unroll
    for (int off = 16; off; off >>= 1) {
        float ov[4]; int oi[4];
        ov[0] = __shfl_xor_sync(0xffffffffu, t0, off); oi[0] = __shfl_xor_sync(0xffffffffu, i0, off);
        ov[1] = __shfl_xor_sync(0xffffffffu, t1, off); oi[1] = __shfl_xor_sync(0xffffffffu, i1, off);
        ov[2] = __shfl_xor_sync(0xffffffffu, t2, off); oi[2] = __shfl_xor_sync(0xffffffffu, i2, off);
        ov[3] = __shfl_xor_sync(0xffffffffu, t3, off); oi[3] = __shfl_xor_sync(0xffffffffu, i3, off);
#pragma unroll
        for (int c = 0; c < 4; c++) {
            const float v = ov[c]; const int ix = oi[c];
            const bool w3 = (v > t3) || (v == t3 && ix < i3);
            if (w3) {
                const bool w1 = (v > t1) || (v == t1 && ix < i1);
                if (w1) {
                    const bool w0 = (v > t0) || (v == t0 && ix < i0);
                    if (w0) { t3=t2;i3=i2; t2=t1;i2=i1; t1=t0;i1=i0; t0=v;i0=ix; }
                    else    { t3=t2;i3=i2; t2=t1;i2=i1; t1=v;i1=ix; }
                } else {
                    const bool w2 = (v > t2) || (v == t2 && ix < i2);
                    if (w2) { t3=t2;i3=i2; t2=v;i2=ix; }
                    else    { t3=v;i3=ix; }
                }
            }
        }
    }

    const float m = t0;
    float sum = 0.f;
#pragma unroll 8
    for (int s = lane; s < SS; s += 32) sum += expf(L[s] - m);
#pragma unroll
    for (int off = 16; off; off >>= 1) sum += __shfl_xor_sync(0xffffffffu, sum, off);

    if (lane == 0) {
        const float inv = 1.0f / sum;
        g_tidx[pair * 4 + 0] = i0; g_tval[pair * 4 + 0] = expf(t0 - m) * inv;
        g_tidx[pair * 4 + 1] = i1; g_tval[pair * 4 + 1] = expf(t1 - m) * inv;
        g_tidx[pair * 4 + 2] = i2; g_tval[pair * 4 + 2] = expf(t2 - m) * inv;
        g_tidx[pair * 4 + 3] = i3; g_tval[pair * 4 + 3] = expf(t3 - m) * inv;
    }
}

// ---------------- K4: gather+scale+TRANSPOSE into g_inpT ------------------
__global__ __launch_bounds__(256) void k4_gatherT(const float* __restrict__ x) {
    __shared__ float ts[32 * 257];
    const int t  = threadIdx.x;
    const int dc = blockIdx.x;
    const int kslot = blockIdx.y;
    const int e  = blockIdx.z;

    const int brow = t >> 3;
    const int d4   = (t & 7) * 4;
    const int idx  = g_tidx[((brow * EE + e)) * KK + kslot];
    const float val = g_tval[((brow * EE + e)) * KK + kslot];
    const float* src = x + ((size_t)brow * SS + idx) * DD + dc * 256;
#pragma unroll
    for (int i = 0; i < 8; i++) {
        const int d = d4 + 32 * i;
        const float4 v = *(const float4*)(src + d);
        float* dst = ts + brow * 257 + d;
        dst[0] = v.x * val; dst[1] = v.y * val; dst[2] = v.z * val; dst[3] = v.w * val;
    }
    __syncthreads();

    float* outb = g_inpT + (size_t)e * (KD * BB)
                + ((size_t)kslot * 1024 + dc * 256) * BB;
    const int bq = t & 7;
#pragma unroll
    for (int j = 0; j < 8; j++) {
        const int d = (t >> 3) + 32 * j;
        float4 v;
        v.x = ts[(bq * 4 + 0) * 257 + d];
        v.y = ts[(bq * 4 + 1) * 257 + d];
        v.z = ts[(bq * 4 + 2) * 257 + d];
        v.w = ts[(bq * 4 + 3) * 257 + d];
        *(float4*)(outb + (size_t)d * BB + bq * 4) = v;
    }
}

// ---------------- T: transpose h [m][e][o] -> hT [e][o][m] ----------------
__global__ __launch_bounds__(256) void t_transpose(const float* __restrict__ h,
                                                   float* __restrict__ hT) {
    __shared__ float ts[32 * 257];
    const int t  = threadIdx.x;
    const int oc = blockIdx.x;
    const int e  = blockIdx.y;

    const int mrow = t >> 3;
    const int o4   = (t & 7) * 4;
    const float* src = h + ((size_t)mrow * EE + e) * OO + oc * 256;
#pragma unroll
    for (int i = 0; i < 8; i++) {
        const int o = o4 + 32 * i;
        const float4 v = *(const float4*)(src + o);
        float* dst = ts + mrow * 257 + o;
        dst[0] = v.x; dst[1] = v.y; dst[2] = v.z; dst[3] = v.w;
    }
    __syncthreads();

    float* outb = hT + (size_t)e * (OO * BB) + (size_t)(oc * 256) * BB;
    const int mq = t & 7;
#pragma unroll
    for (int j = 0; j < 8; j++) {
        const int o = (t >> 3) + 32 * j;
        float4 v;
        v.x = ts[(mq * 4 + 0) * 257 + o];
        v.y = ts[(mq * 4 + 1) * 257 + o];
        v.z = ts[(mq * 4 + 2) * 257 + o];
        v.w = ts[(mq * 4 + 3) * 257 + o];
        *(float4*)(outb + (size_t)o * BB + mq * 4) = v;
    }
}

// ---------------- grouped GEMM -------------------------------------------
// Out[m=32,1024] = AT[e][KDIM][32] x W[e][KDIM,1024]  (+bias, relu?)
// A and W stream through a depth-2 cp.async smem ring, chunk = 16 j per
// K-slice (slot = 80KB). Per chunk: wait_group 0, one barrier, 10 cp.async
// from TWO base pointers (replica strides are compile-time consts).
// Chunk wall ~4096 cyc -> 1-chunk lookahead amply hides DRAM.
// Inner j: 8 broadcast LDS.64 + 1 LDS.128 + 4 splats + 32 FFMA2.
#define CJ 16
#define A_SLOT (8 * CJ * 32)                       // 4096 floats
#define W_SLOT (8 * CJ * 128)                      // 16384 floats
#define RING_SLOT (A_SLOT + W_SLOT)                // 20480 floats
#define GEMM_SMEM_BYTES (2 * RING_SLOT * 4)        // 163,840

template <int KDIM>
__global__ __launch_bounds__(512) void gemm_kernel(const float* __restrict__ AT,
                                                   const float* __restrict__ W,
                                                   const float* __restrict__ bias,
                                                   float* __restrict__ Out,
                                                   int doRelu) {
    constexpr int KPS    = KDIM / 8;
    constexpr int CHUNKS = KPS / CJ;
    static_assert(KPS % CJ == 0, "chunking");
    extern __shared__ __align__(16) float sm[];

    const int tid  = threadIdx.x;
    const int lane = tid & 31;
    const int w    = tid >> 5;
    const int rg   = w & 1;
    const int ks   = w >> 1;
    const int e    = blockIdx.y;
    const float* Ab = AT + (size_t)e * KDIM * BB;
    const float* Wb = W + (size_t)e * KDIM * OO + blockIdx.x * 128;

    // producer bases (replicas i are constant strides from these)
    const int kkA = tid >> 3;                      // 0..63 = slice(0..3)*CJ + j
    const int m4A = (tid & 7) * 4;
    const float* srcA = Ab + ((size_t)(kkA >> 4) * KPS + (kkA & 15)) * BB + m4A;
    const unsigned dstA = (unsigned)(kkA * 32 + m4A) * 4;
    const int kkW = tid >> 5;                      // 0..15 = j
    const int c4W = (tid & 31) * 4;
    const float* srcW = Wb + (size_t)kkW * OO + c4W;
    const unsigned dstW = (unsigned)(A_SLOT + kkW * 128 + c4W) * 4;
    const unsigned smBase = smem_u32(sm);

    int pslot = 0;
    auto issueChunk = [&]() {
        const unsigned base = smBase + pslot * (RING_SLOT * 4);
        cp_async16(base + dstA, srcA);                                  // slices 0-3
        cp_async16(base + dstA + 64 * 32 * 4, srcA + (size_t)4 * KPS * BB);  // slices 4-7
#pragma unroll
        for (int i = 0; i < 8; i++)
            cp_async16(base + dstW + i * (CJ * 128 * 4),
                       srcW + (size_t)i * KPS * OO);
        srcA += CJ * BB;
        srcW += CJ * OO;
        cp_commit();
        pslot ^= 1;
    };

    issueChunk();

    F2 acc[32];
#pragma unroll
    for (int i = 0; i < 32; i++) acc[i].u = 0ull;

    int cslot = 0;
    for (int c = 0; c < CHUNKS; c++) {
        cp_wait0();
        __syncthreads();
        if (c + 1 < CHUNKS) issueChunk();

        const float* slot = sm + cslot * RING_SLOT;
        cslot ^= 1;
        const float* As = slot + (ks * CJ) * 32 + rg * 16;
        const float* Ws = slot + A_SLOT + (ks * CJ) * 128 + lane * 4;
#pragma unroll
        for (int j = 0; j < CJ; j++) {
            const float4 q = *(const float4*)(Ws + j * 128);      // LDS.128
            const F2* ar = (const F2*)(As + j * 32);
            const F2 b0 = fsplat(q.x), b1 = fsplat(q.y),
                     b2 = fsplat(q.z), b3 = fsplat(q.w);
#pragma unroll
            for (int rp = 0; rp < 8; rp++) {
                const F2 a = ar[rp];               // broadcast LDS.64
                ffma2(acc[rp * 4 + 0], a, b0);
                ffma2(acc[rp * 4 + 1], a, b1);
                ffma2(acc[rp * 4 + 2], a, b2);
                ffma2(acc[rp * 4 + 3], a, b3);
            }
        }
    }

    // epilogue: reduce 8 K-slices via smem, bias (+relu), store [m][e][o]
    F2* buf = (F2*)sm;
#pragma unroll
    for (int rp = 0; rp < 8; rp++) {
        __syncthreads();
#pragma unroll
        for (int c = 0; c < 4; c++)
            buf[((ks * 2 + rg) * 32 + lane) * 4 + c] = acc[rp * 4 + c];
        __syncthreads();
        if (tid < 256) {
            const int rrg = tid >> 7;
            const int col = tid & 127;
            const int li  = col >> 2;
            const int ci  = col & 3;
            float sx = 0.f, sy = 0.f;
#pragma unroll
            for (int kss = 0; kss < 8; kss++) {
                const F2 v = buf[((kss * 2 + rrg) * 32 + li) * 4 + ci];
                sx += v.f.x; sy += v.f.y;
            }
            const int occol = blockIdx.x * 128 + col;
            const float bv = bias[e * OO + occol];
            sx += bv; sy += bv;
            if (doRelu) { sx = fmaxf(sx, 0.f); sy = fmaxf(sy, 0.f); }
            const int r0 = rrg * 16 + 2 * rp;
            Out[((size_t)r0 * EE + e) * OO + occol] = sx;
            Out[((size_t)(r0 + 1) * EE + e) * OO + occol] = sy;
        }
    }
}

// ---------------- launch ----------------
extern "C" void kernel_launch(void* const* d_in, const int* in_sizes, int n_in,
                              void* d_out, int out_size) {
    const float* x  = (const float*)d_in[0];
    const float* Wg = (const float*)d_in[1];
    // d_in[2] = bg: constant over the softmax (token) axis -> cancels exactly.
    const float* W1 = (const float*)d_in[3];
    const float* b1 = (const float*)d_in[4];
    const float* W2 = (const float*)d_in[5];
    const float* b2 = (const float*)d_in[6];
    const float* W3 = (const float*)d_in[7];
    const float* b3 = (const float*)d_in[8];
    float* out = (float*)d_out;

    void *pInpT=nullptr, *pH1=nullptr, *pH1T=nullptr, *pH2=nullptr, *pH2T=nullptr;
    cudaGetSymbolAddress(&pInpT, g_inpT);
    cudaGetSymbolAddress(&pH1,  g_h1);
    cudaGetSymbolAddress(&pH1T, g_h1T);
    cudaGetSymbolAddress(&pH2,  g_h2);
    cudaGetSymbolAddress(&pH2T, g_h2T);

    cudaFuncSetAttribute(k1_logits, cudaFuncAttributeMaxDynamicSharedMemorySize, K1_SMEM_BYTES);
    cudaFuncSetAttribute(gemm_kernel<KD>, cudaFuncAttributeMaxDynamicSharedMemorySize, GEMM_SMEM_BYTES);
    cudaFuncSetAttribute(gemm_kernel<OO>, cudaFuncAttributeMaxDynamicSharedMemorySize, GEMM_SMEM_BYTES);

    k1_logits<<<BS / 512, 256, K1_SMEM_BYTES>>>(x, Wg);
    k2_topk<<<(BB * EE) / 8, 256>>>();
    k4_gatherT<<<dim3(4, KK, EE), 256>>>(x);
    gemm_kernel<KD><<<dim3(8, EE), 512, GEMM_SMEM_BYTES>>>((const float*)pInpT, W1, b1, (float*)pH1, 1);
    t_transpose<<<dim3(4, EE), 256>>>((const float*)pH1, (float*)pH1T);
    gemm_kernel<OO><<<dim3(8, EE), 512, GEMM_SMEM_BYTES>>>((const float*)pH1T, W2, b2, (float*)pH2, 1);
    t_transpose<<<dim3(4, EE), 256>>>((const float*)pH2, (float*)pH2T);
    gemm_kernel<OO><<<dim3(8, EE), 512, GEMM_SMEM_BYTES>>>((const float*)pH2T, W3, b3, out, 0);
}